// round 1
// baseline (speedup 1.0000x reference)
#include <cuda_runtime.h>
#include <math.h>

#define S    2048
#define H    1024
#define NH   16
#define HD   64
#define H3   3072
#define E    8
#define II   4096
#define CAP  1024
#define NTOK S

// ---------------- scratch (device globals; no allocation allowed) ----------------
__device__ float g_xn  [S*H];
__device__ float g_qkv [S*H3];
__device__ float g_attn[S*H];
__device__ float g_x1  [S*H];
__device__ float g_xn2 [S*H];
__device__ float g_Xg  [E*CAP*H];
__device__ float g_G   [(size_t)E*CAP*II];
__device__ float g_U   [(size_t)E*CAP*II];
__device__ float g_Y   [E*CAP*H];

__device__ int   g_e1[NTOK], g_e2[NTOK];
__device__ float g_w1[NTOK], g_w2[NTOK];
__device__ int   g_slot1[NTOK], g_slot2[NTOK];
__device__ int   g_valid1[NTOK], g_valid2[NTOK];
__device__ int   g_tok[E*CAP];
__device__ int   g_count[E];        // uncapped (for aux loss)
__device__ int   g_count_used[E];   // capped at CAP (GEMM bound)

// ---------------- RMSNorm ----------------
__global__ void rmsnorm_kernel(const float* __restrict__ x,
                               const float* __restrict__ w,
                               float* __restrict__ out) {
    int row = blockIdx.x;
    const float* xr = x + (size_t)row * H;
    float s = 0.f;
    for (int i = threadIdx.x; i < H; i += 256) { float v = xr[i]; s += v * v; }
    __shared__ float red[256];
    red[threadIdx.x] = s; __syncthreads();
    for (int off = 128; off > 0; off >>= 1) {
        if (threadIdx.x < off) red[threadIdx.x] += red[threadIdx.x + off];
        __syncthreads();
    }
    float inv = rsqrtf(red[0] / (float)H + 1e-6f);
    for (int i = threadIdx.x; i < H; i += 256)
        out[(size_t)row * H + i] = xr[i] * inv * w[i];
}

// ---------------- SGEMM: C[M,N] = A[M,K] * B[N,K]^T (+residual) ----------------
// 128x128 tile, BK=8, 256 threads, 8x8 per thread. grid.z = expert (batched).
__global__ void __launch_bounds__(256)
sgemm_abt_kernel(const float* __restrict__ A, const float* __restrict__ B,
                 float* __restrict__ C, const float* __restrict__ residual,
                 int M, int N, int K,
                 size_t aStride, size_t bStride, size_t cStride,
                 const int* __restrict__ counts) {
    int z = blockIdx.z;
    if (counts && (int)(blockIdx.y * 128) >= counts[z]) return;
    A += (size_t)z * aStride;
    B += (size_t)z * bStride;
    C += (size_t)z * cStride;

    __shared__ float As[8][128];
    __shared__ float Bs[8][128];

    int tid = threadIdx.x;
    int tx = tid & 15, ty = tid >> 4;
    int lRow = tid >> 1;
    int lK   = (tid & 1) << 2;

    const float* aP = A + (size_t)(blockIdx.y * 128 + lRow) * K + lK;
    const float* bP = B + (size_t)(blockIdx.x * 128 + lRow) * K + lK;

    float acc[8][8];
    #pragma unroll
    for (int i = 0; i < 8; i++)
        #pragma unroll
        for (int j = 0; j < 8; j++) acc[i][j] = 0.f;

    for (int kt = 0; kt < K; kt += 8) {
        float4 av = *(const float4*)aP;
        float4 bv = *(const float4*)bP;
        As[lK + 0][lRow] = av.x; As[lK + 1][lRow] = av.y;
        As[lK + 2][lRow] = av.z; As[lK + 3][lRow] = av.w;
        Bs[lK + 0][lRow] = bv.x; Bs[lK + 1][lRow] = bv.y;
        Bs[lK + 2][lRow] = bv.z; Bs[lK + 3][lRow] = bv.w;
        __syncthreads();
        #pragma unroll
        for (int k = 0; k < 8; k++) {
            float4 a0 = *(const float4*)&As[k][ty * 8];
            float4 a1 = *(const float4*)&As[k][ty * 8 + 4];
            float4 b0 = *(const float4*)&Bs[k][tx * 8];
            float4 b1 = *(const float4*)&Bs[k][tx * 8 + 4];
            float ra[8] = {a0.x, a0.y, a0.z, a0.w, a1.x, a1.y, a1.z, a1.w};
            float rb[8] = {b0.x, b0.y, b0.z, b0.w, b1.x, b1.y, b1.z, b1.w};
            #pragma unroll
            for (int i = 0; i < 8; i++)
                #pragma unroll
                for (int j = 0; j < 8; j++)
                    acc[i][j] = fmaf(ra[i], rb[j], acc[i][j]);
        }
        __syncthreads();
        aP += 8; bP += 8;
    }

    int rowBase = blockIdx.y * 128 + ty * 8;
    int colBase = blockIdx.x * 128 + tx * 8;
    #pragma unroll
    for (int i = 0; i < 8; i++) {
        size_t off = (size_t)(rowBase + i) * N + colBase;
        if (residual) {
            #pragma unroll
            for (int j = 0; j < 8; j++) C[off + j] = acc[i][j] + residual[off + j];
        } else {
            *(float4*)&C[off]     = make_float4(acc[i][0], acc[i][1], acc[i][2], acc[i][3]);
            *(float4*)&C[off + 4] = make_float4(acc[i][4], acc[i][5], acc[i][6], acc[i][7]);
        }
    }
}

// ---------------- RoPE in-place on q,k of qkv buffer ----------------
__global__ void rope_kernel(float* __restrict__ qkv) {
    int srow = blockIdx.x;
    float* row = qkv + (size_t)srow * H3;
    for (int it = threadIdx.x; it < 1024; it += 256) {
        int part = it >> 9;          // 0=q, 1=k
        int rem  = it & 511;
        int h    = rem >> 5;
        int d    = rem & 31;         // pair index
        float invf = powf(10000.f, -2.f * (float)d / 64.f);
        float ang  = (float)srow * invf;
        float sn, cs;
        sincosf(ang, &sn, &cs);
        float* p = row + part * H + h * 64;
        float x0 = p[d], x1 = p[d + 32];
        p[d]      = x0 * cs - x1 * sn;
        p[d + 32] = x1 * cs + x0 * sn;
    }
}

// ---------------- causal attention, one (query,head) per block ----------------
__global__ void attn_kernel(const float* __restrict__ qkv, float* __restrict__ out) {
    int i = blockIdx.x;   // query index
    int h = blockIdx.y;   // head
    __shared__ float qs[64];
    __shared__ float sc[S];
    __shared__ float red[256];
    __shared__ float po[4][64];
    int tid = threadIdx.x;

    if (tid < 64) qs[tid] = qkv[(size_t)i * H3 + h * 64 + tid] * 0.125f; // 1/sqrt(64)
    __syncthreads();

    float lmax = -1e30f;
    for (int j = tid; j <= i; j += 256) {
        const float4* kp = (const float4*)(qkv + (size_t)j * H3 + H + h * 64);
        float dot = 0.f;
        #pragma unroll
        for (int t = 0; t < 16; t++) {
            float4 kv = kp[t];
            dot += kv.x * qs[4 * t] + kv.y * qs[4 * t + 1]
                 + kv.z * qs[4 * t + 2] + kv.w * qs[4 * t + 3];
        }
        sc[j] = dot;
        lmax = fmaxf(lmax, dot);
    }
    red[tid] = lmax; __syncthreads();
    for (int off = 128; off > 0; off >>= 1) {
        if (tid < off) red[tid] = fmaxf(red[tid], red[tid + off]);
        __syncthreads();
    }
    float mx = red[0];
    __syncthreads();

    float lsum = 0.f;
    for (int j = tid; j <= i; j += 256) {
        float e = __expf(sc[j] - mx);
        sc[j] = e;
        lsum += e;
    }
    red[tid] = lsum; __syncthreads();
    for (int off = 128; off > 0; off >>= 1) {
        if (tid < off) red[tid] += red[tid + off];
        __syncthreads();
    }
    float inv = 1.f / red[0];

    int g = tid >> 6, d = tid & 63;
    float acc = 0.f;
    for (int j = g; j <= i; j += 4)
        acc += sc[j] * qkv[(size_t)j * H3 + 2 * H + h * 64 + d];
    po[g][d] = acc;
    __syncthreads();
    if (tid < 64) {
        float v = (po[0][tid] + po[1][tid] + po[2][tid] + po[3][tid]) * inv;
        out[(size_t)i * H + h * 64 + tid] = v;
    }
}

// ---------------- router: logits -> softmax -> top2 ----------------
__global__ void router_kernel(const float* __restrict__ xn2, const float* __restrict__ rw) {
    int n = blockIdx.x;
    int tid = threadIdx.x;
    int e = tid >> 5, lane = tid & 31;
    const float* xr = xn2 + (size_t)n * H;
    const float* wr = rw + (size_t)e * H;
    float s = 0.f;
    for (int k = lane; k < H; k += 32) s += xr[k] * wr[k];
    #pragma unroll
    for (int off = 16; off > 0; off >>= 1) s += __shfl_down_sync(0xffffffff, s, off);
    __shared__ float logit[8];
    if (lane == 0) logit[e] = s;
    __syncthreads();
    if (tid == 0) {
        float mx = logit[0];
        for (int q = 1; q < 8; q++) mx = fmaxf(mx, logit[q]);
        float p[8]; float sum = 0.f;
        for (int q = 0; q < 8; q++) { p[q] = expf(logit[q] - mx); sum += p[q]; }
        for (int q = 0; q < 8; q++) p[q] /= sum;
        int b1 = 0;
        for (int q = 1; q < 8; q++) if (p[q] > p[b1]) b1 = q;
        int b2 = -1;
        for (int q = 0; q < 8; q++) {
            if (q == b1) continue;
            if (b2 < 0 || p[q] > p[b2]) b2 = q;
        }
        float ws = p[b1] + p[b2];
        g_e1[n] = b1; g_e2[n] = b2;
        g_w1[n] = p[b1] / ws; g_w2[n] = p[b2] / ws;
    }
}

// ---------------- slot assignment (deterministic per-expert cumsum) ----------------
__global__ void scan_kernel() {
    int w = threadIdx.x >> 5;   // expert = warp id
    int lane = threadIdx.x & 31;
    int base = 0;
    for (int c = 0; c < NTOK; c += 32) {
        int n = c + lane;
        int is1 = (g_e1[n] == w);
        int is2 = (g_e2[n] == w);
        int flag = is1 | is2;
        unsigned m = __ballot_sync(0xffffffff, flag);
        int pos = base + __popc(m & ((1u << lane) - 1u));
        if (flag) {
            int valid = pos < CAP;
            if (is1) { g_slot1[n] = pos; g_valid1[n] = valid; }
            else     { g_slot2[n] = pos; g_valid2[n] = valid; }
            if (valid) g_tok[w * CAP + pos] = n;
        }
        base += __popc(m);
    }
    if (lane == 0) {
        g_count[w] = base;
        g_count_used[w] = base < CAP ? base : CAP;
    }
}

// ---------------- gather xn2 rows into per-expert contiguous buffers ----------------
__global__ void gather_kernel() {
    int e = blockIdx.x >> 10;
    int slot = blockIdx.x & 1023;
    if (slot >= g_count_used[e]) return;
    int n = g_tok[e * CAP + slot];
    const float4* src = (const float4*)(g_xn2 + (size_t)n * H);
    float4* dst = (float4*)(g_Xg + ((size_t)e * CAP + slot) * H);
    dst[threadIdx.x] = src[threadIdx.x];  // 256 threads x float4 = 1024 floats
}

// ---------------- act = silu(G) * U  (in-place into G) ----------------
__global__ void silu_kernel() {
    size_t idx = (size_t)blockIdx.x * 256 + threadIdx.x;
    int e   = (int)(idx / ((size_t)CAP * II));
    int row = (int)((idx / II) % CAP);
    if (row >= g_count_used[e]) return;
    float g = g_G[idx], u = g_U[idx];
    float sg = g / (1.f + __expf(-g));
    g_G[idx] = sg * u;
}

// ---------------- combine: out = x1 + w1*Y[e1,slot1] + w2*Y[e2,slot2] ----------------
__global__ void combine_kernel(float* __restrict__ out) {
    int n = blockIdx.x;
    int e1 = g_e1[n], e2 = g_e2[n];
    int s1 = g_slot1[n], s2 = g_slot2[n];
    int v1 = g_valid1[n], v2 = g_valid2[n];
    float w1 = g_w1[n], w2 = g_w2[n];
    const float* y1 = g_Y + ((size_t)e1 * CAP + (v1 ? s1 : 0)) * H;
    const float* y2 = g_Y + ((size_t)e2 * CAP + (v2 ? s2 : 0)) * H;
    for (int h = threadIdx.x; h < H; h += 256) {
        float acc = g_x1[(size_t)n * H + h];
        if (v1) acc += w1 * y1[h];
        if (v2) acc += w2 * y2[h];
        out[(size_t)n * H + h] = acc;
    }
}

// ---------------- aux loss (unbiased var of expert-load fractions * E) ----------------
__global__ void aux_kernel(float* __restrict__ out, int out_size) {
    if (out_size <= S * H) return;
    float m[8], mu = 0.f;
    for (int e = 0; e < 8; e++) { m[e] = (float)g_count[e] / (float)NTOK; mu += m[e]; }
    mu *= 0.125f;
    float var = 0.f;
    for (int e = 0; e < 8; e++) { float d = m[e] - mu; var += d * d; }
    var /= 7.f;
    out[S * H] = var * 8.f;
}

// ---------------- launch ----------------
extern "C" void kernel_launch(void* const* d_in, const int* in_sizes, int n_in,
                              void* d_out, int out_size) {
    const float* x     = (const float*)d_in[0];
    const float* anw   = (const float*)d_in[1];
    const float* qkv_w = (const float*)d_in[2];
    const float* o_w   = (const float*)d_in[3];
    const float* fnw   = (const float*)d_in[4];
    const float* rw    = (const float*)d_in[5];
    const float* wg    = (const float*)d_in[6];
    const float* wu    = (const float*)d_in[7];
    const float* wd    = (const float*)d_in[8];
    float* out = (float*)d_out;

    float *p_xn, *p_qkv, *p_attn, *p_x1, *p_xn2, *p_Xg, *p_G, *p_U, *p_Y;
    int* p_cu;
    cudaGetSymbolAddress((void**)&p_xn,  g_xn);
    cudaGetSymbolAddress((void**)&p_qkv, g_qkv);
    cudaGetSymbolAddress((void**)&p_attn,g_attn);
    cudaGetSymbolAddress((void**)&p_x1,  g_x1);
    cudaGetSymbolAddress((void**)&p_xn2, g_xn2);
    cudaGetSymbolAddress((void**)&p_Xg,  g_Xg);
    cudaGetSymbolAddress((void**)&p_G,   g_G);
    cudaGetSymbolAddress((void**)&p_U,   g_U);
    cudaGetSymbolAddress((void**)&p_Y,   g_Y);
    cudaGetSymbolAddress((void**)&p_cu,  g_count_used);

    // attention path
    rmsnorm_kernel<<<S, 256>>>(x, anw, p_xn);
    sgemm_abt_kernel<<<dim3(H3 / 128, S / 128, 1), 256>>>(
        p_xn, qkv_w, p_qkv, nullptr, S, H3, H, 0, 0, 0, nullptr);
    rope_kernel<<<S, 256>>>(p_qkv);
    attn_kernel<<<dim3(S, NH), 256>>>(p_qkv, p_attn);
    sgemm_abt_kernel<<<dim3(H / 128, S / 128, 1), 256>>>(
        p_attn, o_w, p_x1, x, S, H, H, 0, 0, 0, nullptr);

    // MoE path
    rmsnorm_kernel<<<S, 256>>>(p_x1, fnw, p_xn2);
    router_kernel<<<S, 256>>>(p_xn2, rw);
    scan_kernel<<<1, 256>>>();
    gather_kernel<<<E * CAP, 256>>>();
    sgemm_abt_kernel<<<dim3(II / 128, CAP / 128, E), 256>>>(
        p_Xg, wg, p_G, nullptr, CAP, II, H,
        (size_t)CAP * H, (size_t)II * H, (size_t)CAP * II, p_cu);
    sgemm_abt_kernel<<<dim3(II / 128, CAP / 128, E), 256>>>(
        p_Xg, wu, p_U, nullptr, CAP, II, H,
        (size_t)CAP * H, (size_t)II * H, (size_t)CAP * II, p_cu);
    silu_kernel<<<(E * CAP * (II / 256)), 256>>>();
    sgemm_abt_kernel<<<dim3(H / 128, CAP / 128, E), 256>>>(
        p_G, wd, p_Y, nullptr, CAP, H, II,
        (size_t)CAP * II, (size_t)H * II, (size_t)CAP * H, p_cu);
    combine_kernel<<<S, 256>>>(out);
    aux_kernel<<<1, 1>>>(out, out_size);
}

// round 3
// speedup vs baseline: 1.9054x; 1.9054x over previous
#include <cuda_runtime.h>
#include <math.h>

#define S    2048
#define H    1024
#define NH   16
#define HD   64
#define H3   3072
#define E    8
#define II   4096
#define CAP  1024
#define NTOK S

// ---------------- scratch (device globals; no allocation allowed) ----------------
__device__ float g_xn  [S*H];
__device__ float g_qkv [S*H3];
__device__ float g_attn[S*H];
__device__ float g_x1  [S*H];
__device__ float g_xn2 [S*H];
__device__ float g_Xg  [E*CAP*H];
__device__ float g_G   [(size_t)E*CAP*II];
__device__ float g_U   [(size_t)E*CAP*II];
__device__ float g_Y   [E*CAP*H];

__device__ int   g_e1[NTOK], g_e2[NTOK];
__device__ float g_w1[NTOK], g_w2[NTOK];
__device__ int   g_slot1[NTOK], g_slot2[NTOK];
__device__ int   g_valid1[NTOK], g_valid2[NTOK];
__device__ int   g_tok[E*CAP];
__device__ int   g_count[E];
__device__ int   g_count_used[E];

// ---------------- RMSNorm ----------------
__global__ void rmsnorm_kernel(const float* __restrict__ x,
                               const float* __restrict__ w,
                               float* __restrict__ out) {
    int row = blockIdx.x;
    const float* xr = x + (size_t)row * H;
    float s = 0.f;
    for (int i = threadIdx.x; i < H; i += 256) { float v = xr[i]; s += v * v; }
    __shared__ float red[256];
    red[threadIdx.x] = s; __syncthreads();
    for (int off = 128; off > 0; off >>= 1) {
        if (threadIdx.x < off) red[threadIdx.x] += red[threadIdx.x + off];
        __syncthreads();
    }
    float inv = rsqrtf(red[0] / (float)H + 1e-6f);
    for (int i = threadIdx.x; i < H; i += 256)
        out[(size_t)row * H + i] = xr[i] * inv * w[i];
}

// ------------- 3xTF32 tensor-core GEMM: C[M,N] = A[M,K]*B[N,K]^T (+residual) ------
// 128x128 block tile, k-tile 16, 8 warps (2x4) of 64x32 warp tiles.
// Each element split hi/lo (tf32); products ah*bh + ah*bl + al*bh -> ~fp32 accuracy.
#define CVT_TF32(u, f) asm("cvt.rna.tf32.f32 %0, %1;" : "=r"(u) : "f"(f))

__device__ __forceinline__ void split_tf32(float f, unsigned& hi, unsigned& lo) {
    CVT_TF32(hi, f);
    float r = f - __uint_as_float(hi);
    CVT_TF32(lo, r);
}

#define MMA_TF32(acc, a, b)                                              \
    asm volatile(                                                        \
        "mma.sync.aligned.m16n8k8.row.col.f32.tf32.tf32.f32 "            \
        "{%0,%1,%2,%3}, {%4,%5,%6,%7}, {%8,%9}, {%0,%1,%2,%3};"          \
        : "+f"(acc[0]), "+f"(acc[1]), "+f"(acc[2]), "+f"(acc[3])         \
        : "r"(a[0]), "r"(a[1]), "r"(a[2]), "r"(a[3]), "r"(b[0]), "r"(b[1]))

__global__ void __launch_bounds__(256)
tf32x3_gemm_kernel(const float* __restrict__ A, const float* __restrict__ B,
                   float* __restrict__ C, const float* __restrict__ residual,
                   int N, int K,
                   size_t aStride, size_t bStride, size_t cStride,
                   const int* __restrict__ counts) {
    int z = blockIdx.z;
    if (counts && (int)(blockIdx.y << 7) >= counts[z]) return;
    A += (size_t)z * aStride + ((size_t)blockIdx.y << 7) * K;
    B += (size_t)z * bStride + ((size_t)blockIdx.x << 7) * K;
    C += (size_t)z * cStride;

    __shared__ unsigned sAh[16][136], sAl[16][136];
    __shared__ unsigned sBh[16][136], sBl[16][136];

    const int tid  = threadIdx.x;
    const int lrow = tid >> 2;          // 0..63
    const int lcol = (tid & 3) << 2;    // 0,4,8,12

    const float* aP = A + (size_t)lrow * K + lcol;
    const float* bP = B + (size_t)lrow * K + lcol;
    const size_t rowStep = (size_t)64 * K;

    const int lane = tid & 31;
    const int wid  = tid >> 5;
    const int gid  = lane >> 2, tig = lane & 3;
    const int wm   = (wid >> 2) * 64;
    const int wn   = (wid & 3) * 32;

    float acc[4][4][4];
    #pragma unroll
    for (int i = 0; i < 4; i++)
        #pragma unroll
        for (int j = 0; j < 4; j++)
            #pragma unroll
            for (int r = 0; r < 4; r++) acc[i][j][r] = 0.f;

    float4 ra0 = *(const float4*)(aP);
    float4 ra1 = *(const float4*)(aP + rowStep);
    float4 rb0 = *(const float4*)(bP);
    float4 rb1 = *(const float4*)(bP + rowStep);

    const int nk = K >> 4;

    for (int kt = 0; kt < nk; kt++) {
        if (kt) __syncthreads();  // previous tile's consumers done
        {
            unsigned h, l;
            split_tf32(ra0.x, h, l); sAh[lcol+0][lrow] = h; sAl[lcol+0][lrow] = l;
            split_tf32(ra0.y, h, l); sAh[lcol+1][lrow] = h; sAl[lcol+1][lrow] = l;
            split_tf32(ra0.z, h, l); sAh[lcol+2][lrow] = h; sAl[lcol+2][lrow] = l;
            split_tf32(ra0.w, h, l); sAh[lcol+3][lrow] = h; sAl[lcol+3][lrow] = l;
            split_tf32(ra1.x, h, l); sAh[lcol+0][lrow+64] = h; sAl[lcol+0][lrow+64] = l;
            split_tf32(ra1.y, h, l); sAh[lcol+1][lrow+64] = h; sAl[lcol+1][lrow+64] = l;
            split_tf32(ra1.z, h, l); sAh[lcol+2][lrow+64] = h; sAl[lcol+2][lrow+64] = l;
            split_tf32(ra1.w, h, l); sAh[lcol+3][lrow+64] = h; sAl[lcol+3][lrow+64] = l;
            split_tf32(rb0.x, h, l); sBh[lcol+0][lrow] = h; sBl[lcol+0][lrow] = l;
            split_tf32(rb0.y, h, l); sBh[lcol+1][lrow] = h; sBl[lcol+1][lrow] = l;
            split_tf32(rb0.z, h, l); sBh[lcol+2][lrow] = h; sBl[lcol+2][lrow] = l;
            split_tf32(rb0.w, h, l); sBh[lcol+3][lrow] = h; sBl[lcol+3][lrow] = l;
            split_tf32(rb1.x, h, l); sBh[lcol+0][lrow+64] = h; sBl[lcol+0][lrow+64] = l;
            split_tf32(rb1.y, h, l); sBh[lcol+1][lrow+64] = h; sBl[lcol+1][lrow+64] = l;
            split_tf32(rb1.z, h, l); sBh[lcol+2][lrow+64] = h; sBl[lcol+2][lrow+64] = l;
            split_tf32(rb1.w, h, l); sBh[lcol+3][lrow+64] = h; sBl[lcol+3][lrow+64] = l;
        }
        __syncthreads();

        if (kt + 1 < nk) {
            const float* aN = aP + (size_t)(kt + 1) * 16;
            const float* bN = bP + (size_t)(kt + 1) * 16;
            ra0 = *(const float4*)(aN);
            ra1 = *(const float4*)(aN + rowStep);
            rb0 = *(const float4*)(bN);
            rb1 = *(const float4*)(bN + rowStep);
        }

        #pragma unroll
        for (int kf = 0; kf < 2; kf++) {
            const int k0 = kf << 3;
            unsigned ah[4][4], al[4][4], bh[4][2], bl[4][2];
            #pragma unroll
            for (int mt = 0; mt < 4; mt++) {
                int m = wm + (mt << 4) + gid;
                ah[mt][0] = sAh[k0 + tig    ][m];
                ah[mt][1] = sAh[k0 + tig    ][m + 8];
                ah[mt][2] = sAh[k0 + tig + 4][m];
                ah[mt][3] = sAh[k0 + tig + 4][m + 8];
                al[mt][0] = sAl[k0 + tig    ][m];
                al[mt][1] = sAl[k0 + tig    ][m + 8];
                al[mt][2] = sAl[k0 + tig + 4][m];
                al[mt][3] = sAl[k0 + tig + 4][m + 8];
            }
            #pragma unroll
            for (int nt = 0; nt < 4; nt++) {
                int n = wn + (nt << 3) + gid;
                bh[nt][0] = sBh[k0 + tig    ][n];
                bh[nt][1] = sBh[k0 + tig + 4][n];
                bl[nt][0] = sBl[k0 + tig    ][n];
                bl[nt][1] = sBl[k0 + tig + 4][n];
            }
            #pragma unroll
            for (int mt = 0; mt < 4; mt++)
                #pragma unroll
                for (int nt = 0; nt < 4; nt++) {
                    MMA_TF32(acc[mt][nt], al[mt], bh[nt]);
                    MMA_TF32(acc[mt][nt], ah[mt], bl[nt]);
                    MMA_TF32(acc[mt][nt], ah[mt], bh[nt]);
                }
        }
        aP += 0; bP += 0; // pointers advanced via kt*16 arithmetic
    }

    // epilogue
    const int rBase = (blockIdx.y << 7) + wm;
    const int cBase = (blockIdx.x << 7) + wn;
    #pragma unroll
    for (int mt = 0; mt < 4; mt++) {
        int r0 = rBase + (mt << 4) + gid;
        #pragma unroll
        for (int nt = 0; nt < 4; nt++) {
            int c = cBase + (nt << 3) + (tig << 1);
            size_t o0 = (size_t)r0 * N + c;
            size_t o1 = o0 + (size_t)8 * N;
            if (residual) {
                float2 q0 = *(const float2*)&residual[o0];
                float2 q1 = *(const float2*)&residual[o1];
                *(float2*)&C[o0] = make_float2(acc[mt][nt][0] + q0.x, acc[mt][nt][1] + q0.y);
                *(float2*)&C[o1] = make_float2(acc[mt][nt][2] + q1.x, acc[mt][nt][3] + q1.y);
            } else {
                *(float2*)&C[o0] = make_float2(acc[mt][nt][0], acc[mt][nt][1]);
                *(float2*)&C[o1] = make_float2(acc[mt][nt][2], acc[mt][nt][3]);
            }
        }
    }
}

// ---------------- RoPE in-place on q,k of qkv buffer ----------------
__global__ void rope_kernel(float* __restrict__ qkv) {
    int srow = blockIdx.x;
    float* row = qkv + (size_t)srow * H3;
    for (int it = threadIdx.x; it < 1024; it += 256) {
        int part = it >> 9;
        int rem  = it & 511;
        int h    = rem >> 5;
        int d    = rem & 31;
        float invf = powf(10000.f, -2.f * (float)d / 64.f);
        float ang  = (float)srow * invf;
        float sn, cs;
        sincosf(ang, &sn, &cs);
        float* p = row + part * H + h * 64;
        float x0 = p[d], x1 = p[d + 32];
        p[d]      = x0 * cs - x1 * sn;
        p[d + 32] = x1 * cs + x0 * sn;
    }
}

// ---------------- flash attention: 64-query x 64-key tiles, fp32 ----------------
__global__ void __launch_bounds__(256)
flash_attn_kernel(const float* __restrict__ qkv, float* __restrict__ out) {
    const int qt = blockIdx.x;
    const int h  = blockIdx.y;
    const int qbase = qt << 6;

    __shared__ float Qs [64][64];
    __shared__ float KVs[64][64];
    __shared__ float Ps [64][64];

    const int tid = threadIdx.x;
    const int ty = tid >> 4, tx = tid & 15;

    #pragma unroll
    for (int rep = 0; rep < 4; rep++) {
        int f = (rep << 8) + tid;
        int q = f >> 4;
        int d4 = (f & 15) << 2;
        float4 v = *(const float4*)&qkv[(size_t)(qbase + q) * H3 + h * 64 + d4];
        Qs[d4+0][q] = v.x * 0.125f;
        Qs[d4+1][q] = v.y * 0.125f;
        Qs[d4+2][q] = v.z * 0.125f;
        Qs[d4+3][q] = v.w * 0.125f;
    }

    float m_i[4], l_i[4], oacc[4][4];
    #pragma unroll
    for (int i = 0; i < 4; i++) {
        m_i[i] = -1e30f; l_i[i] = 0.f;
        #pragma unroll
        for (int j = 0; j < 4; j++) oacc[i][j] = 0.f;
    }

    for (int kt = 0; kt <= qt; kt++) {
        const int kbase = kt << 6;
        __syncthreads();
        #pragma unroll
        for (int rep = 0; rep < 4; rep++) {
            int f = (rep << 8) + tid;
            int k = f >> 4;
            int d4 = (f & 15) << 2;
            float4 v = *(const float4*)&qkv[(size_t)(kbase + k) * H3 + H + h * 64 + d4];
            KVs[d4+0][k] = v.x; KVs[d4+1][k] = v.y;
            KVs[d4+2][k] = v.z; KVs[d4+3][k] = v.w;
        }
        __syncthreads();

        float s[4][4];
        #pragma unroll
        for (int i = 0; i < 4; i++)
            #pragma unroll
            for (int j = 0; j < 4; j++) s[i][j] = 0.f;
        #pragma unroll 8
        for (int d = 0; d < 64; d++) {
            float4 a = *(const float4*)&Qs [d][ty << 2];
            float4 b = *(const float4*)&KVs[d][tx << 2];
            float av[4] = {a.x, a.y, a.z, a.w};
            float bv[4] = {b.x, b.y, b.z, b.w};
            #pragma unroll
            for (int i = 0; i < 4; i++)
                #pragma unroll
                for (int j = 0; j < 4; j++)
                    s[i][j] = fmaf(av[i], bv[j], s[i][j]);
        }
        if (kt == qt) {
            #pragma unroll
            for (int i = 0; i < 4; i++)
                #pragma unroll
                for (int j = 0; j < 4; j++)
                    if ((tx << 2) + j > (ty << 2) + i) s[i][j] = -1e30f;
        }

        #pragma unroll
        for (int i = 0; i < 4; i++) {
            float rmax = fmaxf(fmaxf(s[i][0], s[i][1]), fmaxf(s[i][2], s[i][3]));
            #pragma unroll
            for (int off = 8; off > 0; off >>= 1)
                rmax = fmaxf(rmax, __shfl_xor_sync(0xffffffffu, rmax, off));
            float mnew = fmaxf(m_i[i], rmax);
            float corr = __expf(m_i[i] - mnew);
            float rsum = 0.f;
            #pragma unroll
            for (int j = 0; j < 4; j++) {
                float p = __expf(s[i][j] - mnew);
                s[i][j] = p;
                rsum += p;
            }
            #pragma unroll
            for (int off = 8; off > 0; off >>= 1)
                rsum += __shfl_xor_sync(0xffffffffu, rsum, off);
            l_i[i] = l_i[i] * corr + rsum;
            m_i[i] = mnew;
            #pragma unroll
            for (int j = 0; j < 4; j++) oacc[i][j] *= corr;
        }
        __syncthreads();

        #pragma unroll
        for (int rep = 0; rep < 4; rep++) {
            int f = (rep << 8) + tid;
            int k = f >> 4;
            int d4 = (f & 15) << 2;
            float4 v = *(const float4*)&qkv[(size_t)(kbase + k) * H3 + 2 * H + h * 64 + d4];
            *(float4*)&KVs[k][d4] = v;
        }
        #pragma unroll
        for (int i = 0; i < 4; i++)
            #pragma unroll
            for (int j = 0; j < 4; j++)
                Ps[(tx << 2) + j][(ty << 2) + i] = s[i][j];
        __syncthreads();

        #pragma unroll 8
        for (int k = 0; k < 64; k++) {
            float4 a = *(const float4*)&Ps [k][ty << 2];
            float4 b = *(const float4*)&KVs[k][tx << 2];
            float av[4] = {a.x, a.y, a.z, a.w};
            float bv[4] = {b.x, b.y, b.z, b.w};
            #pragma unroll
            for (int i = 0; i < 4; i++)
                #pragma unroll
                for (int j = 0; j < 4; j++)
                    oacc[i][j] = fmaf(av[i], bv[j], oacc[i][j]);
        }
    }

    #pragma unroll
    for (int i = 0; i < 4; i++) {
        float inv = 1.f / l_i[i];
        int q = qbase + (ty << 2) + i;
        float4 v = make_float4(oacc[i][0] * inv, oacc[i][1] * inv,
                               oacc[i][2] * inv, oacc[i][3] * inv);
        *(float4*)&out[(size_t)q * H + h * 64 + (tx << 2)] = v;
    }
}

// ---------------- router ----------------
__global__ void router_kernel(const float* __restrict__ xn2, const float* __restrict__ rw) {
    int n = blockIdx.x;
    int tid = threadIdx.x;
    int e = tid >> 5, lane = tid & 31;
    const float* xr = xn2 + (size_t)n * H;
    const float* wr = rw + (size_t)e * H;
    float s = 0.f;
    for (int k = lane; k < H; k += 32) s += xr[k] * wr[k];
    #pragma unroll
    for (int off = 16; off > 0; off >>= 1) s += __shfl_down_sync(0xffffffff, s, off);
    __shared__ float logit[8];
    if (lane == 0) logit[e] = s;
    __syncthreads();
    if (tid == 0) {
        float mx = logit[0];
        for (int q = 1; q < 8; q++) mx = fmaxf(mx, logit[q]);
        float p[8]; float sum = 0.f;
        for (int q = 0; q < 8; q++) { p[q] = expf(logit[q] - mx); sum += p[q]; }
        for (int q = 0; q < 8; q++) p[q] /= sum;
        int b1 = 0;
        for (int q = 1; q < 8; q++) if (p[q] > p[b1]) b1 = q;
        int b2 = -1;
        for (int q = 0; q < 8; q++) {
            if (q == b1) continue;
            if (b2 < 0 || p[q] > p[b2]) b2 = q;
        }
        float ws = p[b1] + p[b2];
        g_e1[n] = b1; g_e2[n] = b2;
        g_w1[n] = p[b1] / ws; g_w2[n] = p[b2] / ws;
    }
}

// ---------------- slot assignment ----------------
__global__ void scan_kernel() {
    int w = threadIdx.x >> 5;
    int lane = threadIdx.x & 31;
    int base = 0;
    for (int c = 0; c < NTOK; c += 32) {
        int n = c + lane;
        int is1 = (g_e1[n] == w);
        int is2 = (g_e2[n] == w);
        int flag = is1 | is2;
        unsigned m = __ballot_sync(0xffffffff, flag);
        int pos = base + __popc(m & ((1u << lane) - 1u));
        if (flag) {
            int valid = pos < CAP;
            if (is1) { g_slot1[n] = pos; g_valid1[n] = valid; }
            else     { g_slot2[n] = pos; g_valid2[n] = valid; }
            if (valid) g_tok[w * CAP + pos] = n;
        }
        base += __popc(m);
    }
    if (lane == 0) {
        g_count[w] = base;
        g_count_used[w] = base < CAP ? base : CAP;
    }
}

// ---------------- gather ----------------
__global__ void gather_kernel() {
    int e = blockIdx.x >> 10;
    int slot = blockIdx.x & 1023;
    if (slot >= g_count_used[e]) return;
    int n = g_tok[e * CAP + slot];
    const float4* src = (const float4*)(g_xn2 + (size_t)n * H);
    float4* dst = (float4*)(g_Xg + ((size_t)e * CAP + slot) * H);
    dst[threadIdx.x] = src[threadIdx.x];
}

// ---------------- silu ----------------
__global__ void silu_kernel() {
    size_t idx = (size_t)blockIdx.x * 256 + threadIdx.x;
    int e   = (int)(idx / ((size_t)CAP * II));
    int row = (int)((idx / II) % CAP);
    if (row >= g_count_used[e]) return;
    float g = g_G[idx], u = g_U[idx];
    float sg = g / (1.f + __expf(-g));
    g_G[idx] = sg * u;
}

// ---------------- combine ----------------
__global__ void combine_kernel(float* __restrict__ out) {
    int n = blockIdx.x;
    int e1 = g_e1[n], e2 = g_e2[n];
    int s1 = g_slot1[n], s2 = g_slot2[n];
    int v1 = g_valid1[n], v2 = g_valid2[n];
    float w1 = g_w1[n], w2 = g_w2[n];
    const float* y1 = g_Y + ((size_t)e1 * CAP + (v1 ? s1 : 0)) * H;
    const float* y2 = g_Y + ((size_t)e2 * CAP + (v2 ? s2 : 0)) * H;
    for (int h = threadIdx.x; h < H; h += 256) {
        float acc = g_x1[(size_t)n * H + h];
        if (v1) acc += w1 * y1[h];
        if (v2) acc += w2 * y2[h];
        out[(size_t)n * H + h] = acc;
    }
}

// ---------------- aux loss ----------------
__global__ void aux_kernel(float* __restrict__ out, int out_size) {
    if (out_size <= S * H) return;
    float m[8], mu = 0.f;
    for (int e = 0; e < 8; e++) { m[e] = (float)g_count[e] / (float)NTOK; mu += m[e]; }
    mu *= 0.125f;
    float var = 0.f;
    for (int e = 0; e < 8; e++) { float d = m[e] - mu; var += d * d; }
    var /= 7.f;
    out[S * H] = var * 8.f;
}

// ---------------- launch ----------------
extern "C" void kernel_launch(void* const* d_in, const int* in_sizes, int n_in,
                              void* d_out, int out_size) {
    const float* x     = (const float*)d_in[0];
    const float* anw   = (const float*)d_in[1];
    const float* qkv_w = (const float*)d_in[2];
    const float* o_w   = (const float*)d_in[3];
    const float* fnw   = (const float*)d_in[4];
    const float* rw    = (const float*)d_in[5];
    const float* wg    = (const float*)d_in[6];
    const float* wu    = (const float*)d_in[7];
    const float* wd    = (const float*)d_in[8];
    float* out = (float*)d_out;

    float *p_xn, *p_qkv, *p_attn, *p_x1, *p_xn2, *p_Xg, *p_G, *p_U, *p_Y;
    int* p_cu;
    cudaGetSymbolAddress((void**)&p_xn,  g_xn);
    cudaGetSymbolAddress((void**)&p_qkv, g_qkv);
    cudaGetSymbolAddress((void**)&p_attn,g_attn);
    cudaGetSymbolAddress((void**)&p_x1,  g_x1);
    cudaGetSymbolAddress((void**)&p_xn2, g_xn2);
    cudaGetSymbolAddress((void**)&p_Xg,  g_Xg);
    cudaGetSymbolAddress((void**)&p_G,   g_G);
    cudaGetSymbolAddress((void**)&p_U,   g_U);
    cudaGetSymbolAddress((void**)&p_Y,   g_Y);
    cudaGetSymbolAddress((void**)&p_cu,  g_count_used);

    // attention path
    rmsnorm_kernel<<<S, 256>>>(x, anw, p_xn);
    tf32x3_gemm_kernel<<<dim3(H3 / 128, S / 128, 1), 256>>>(
        p_xn, qkv_w, p_qkv, nullptr, H3, H, 0, 0, 0, nullptr);
    rope_kernel<<<S, 256>>>(p_qkv);
    flash_attn_kernel<<<dim3(S / 64, NH), 256>>>(p_qkv, p_attn);
    tf32x3_gemm_kernel<<<dim3(H / 128, S / 128, 1), 256>>>(
        p_attn, o_w, p_x1, x, H, H, 0, 0, 0, nullptr);

    // MoE path
    rmsnorm_kernel<<<S, 256>>>(p_x1, fnw, p_xn2);
    router_kernel<<<S, 256>>>(p_xn2, rw);
    scan_kernel<<<1, 256>>>();
    gather_kernel<<<E * CAP, 256>>>();
    tf32x3_gemm_kernel<<<dim3(II / 128, CAP / 128, E), 256>>>(
        p_Xg, wg, p_G, nullptr, II, H,
        (size_t)CAP * H, (size_t)II * H, (size_t)CAP * II, p_cu);
    tf32x3_gemm_kernel<<<dim3(II / 128, CAP / 128, E), 256>>>(
        p_Xg, wu, p_U, nullptr, II, H,
        (size_t)CAP * H, (size_t)II * H, (size_t)CAP * II, p_cu);
    silu_kernel<<<(E * CAP * (II / 256)), 256>>>();
    tf32x3_gemm_kernel<<<dim3(H / 128, CAP / 128, E), 256>>>(
        p_G, wd, p_Y, nullptr, H, II,
        (size_t)CAP * II, (size_t)H * II, (size_t)CAP * H, p_cu);
    combine_kernel<<<S, 256>>>(out);
    aux_kernel<<<1, 1>>>(out, out_size);
}

// round 4
// speedup vs baseline: 3.2242x; 1.6922x over previous
#include <cuda_runtime.h>
#include <cuda_bf16.h>
#include <math.h>

#define S    2048
#define H    1024
#define NH   16
#define HD   64
#define H3   3072
#define E    8
#define II   4096
#define CAP  1024
#define NTOK S

// ---------------- scratch (device globals; no allocation allowed) ----------------
__device__ float g_xn  [S*H];
__device__ float g_qkv [S*H3];
__device__ float g_attn[S*H];
__device__ float g_x1  [S*H];
__device__ float g_xn2 [S*H];
__device__ float g_Xg  [E*CAP*H];
__device__ float g_G   [(size_t)E*CAP*II];
__device__ float g_U   [(size_t)E*CAP*II];
__device__ float g_Y   [E*CAP*H];

__device__ int   g_e1[NTOK], g_e2[NTOK];
__device__ float g_w1[NTOK], g_w2[NTOK];
__device__ int   g_slot1[NTOK], g_slot2[NTOK];
__device__ int   g_valid1[NTOK], g_valid2[NTOK];
__device__ int   g_tok[E*CAP];
__device__ int   g_count[E];
__device__ int   g_count_used[E];

// ---------------- RMSNorm ----------------
__global__ void rmsnorm_kernel(const float* __restrict__ x,
                               const float* __restrict__ w,
                               float* __restrict__ out) {
    int row = blockIdx.x;
    const float* xr = x + (size_t)row * H;
    float s = 0.f;
    for (int i = threadIdx.x; i < H; i += 256) { float v = xr[i]; s += v * v; }
    __shared__ float red[256];
    red[threadIdx.x] = s; __syncthreads();
    for (int off = 128; off > 0; off >>= 1) {
        if (threadIdx.x < off) red[threadIdx.x] += red[threadIdx.x + off];
        __syncthreads();
    }
    float inv = rsqrtf(red[0] / (float)H + 1e-6f);
    for (int i = threadIdx.x; i < H; i += 256)
        out[(size_t)row * H + i] = xr[i] * inv * w[i];
}

// ------- 3xBF16 tensor-core GEMM: C[M,N] = A[M,K]*B[N,K]^T (+residual) -----------
// 128x128 block tile, k-tile 16, 8 warps (2x4) of 64x32 warp tiles.
// Elements split hi/lo (bf16, packed bf16x2 along k); products ah*bh+ah*bl+al*bh.
// Double-buffered smem, one __syncthreads per k-tile, gmem prefetch before mma.

__device__ __forceinline__ void split2_bf16(float f0, float f1,
                                            unsigned& hi, unsigned& lo) {
    __nv_bfloat16 h0 = __float2bfloat16_rn(f0);
    __nv_bfloat16 h1 = __float2bfloat16_rn(f1);
    float r0 = f0 - __bfloat162float(h0);
    float r1 = f1 - __bfloat162float(h1);
    __nv_bfloat16 l0 = __float2bfloat16_rn(r0);
    __nv_bfloat16 l1 = __float2bfloat16_rn(r1);
    hi = ((unsigned)__bfloat16_as_ushort(h1) << 16) | __bfloat16_as_ushort(h0);
    lo = ((unsigned)__bfloat16_as_ushort(l1) << 16) | __bfloat16_as_ushort(l0);
}

#define MMA_BF16(acc, a, b)                                               \
    asm volatile(                                                         \
        "mma.sync.aligned.m16n8k16.row.col.f32.bf16.bf16.f32 "            \
        "{%0,%1,%2,%3}, {%4,%5,%6,%7}, {%8,%9}, {%0,%1,%2,%3};"           \
        : "+f"(acc[0]), "+f"(acc[1]), "+f"(acc[2]), "+f"(acc[3])          \
        : "r"(a[0]), "r"(a[1]), "r"(a[2]), "r"(a[3]), "r"(b[0]), "r"(b[1]))

__global__ void __launch_bounds__(256)
bf16x3_gemm_kernel(const float* __restrict__ A, const float* __restrict__ B,
                   float* __restrict__ C, const float* __restrict__ residual,
                   int N, int K,
                   size_t aStride, size_t bStride, size_t cStride,
                   const int* __restrict__ counts) {
    int z = blockIdx.z;
    if (counts && (int)(blockIdx.y << 7) >= counts[z]) return;
    A += (size_t)z * aStride + ((size_t)blockIdx.y << 7) * K;
    B += (size_t)z * bStride + ((size_t)blockIdx.x << 7) * K;
    C += (size_t)z * cStride;

    // [buf][k-pair word 0..7][row 0..127 + pad]
    __shared__ unsigned sAh[2][8][136], sAl[2][8][136];
    __shared__ unsigned sBh[2][8][136], sBl[2][8][136];

    const int tid  = threadIdx.x;
    const int lrow = tid >> 2;           // 0..63
    const int lcol = (tid & 3) << 2;     // k offset 0,4,8,12
    const int w0   = (tid & 3) << 1;     // word index 0,2,4,6

    const float* aP = A + (size_t)lrow * K + lcol;
    const float* bP = B + (size_t)lrow * K + lcol;
    const size_t rowStep = (size_t)64 * K;

    const int lane = tid & 31;
    const int wid  = tid >> 5;
    const int gid  = lane >> 2, tig = lane & 3;
    const int wm   = (wid >> 2) * 64;
    const int wn   = (wid & 3) * 32;

    float acc[4][4][4];
    #pragma unroll
    for (int i = 0; i < 4; i++)
        #pragma unroll
        for (int j = 0; j < 4; j++)
            #pragma unroll
            for (int r = 0; r < 4; r++) acc[i][j][r] = 0.f;

    float4 ra0 = *(const float4*)(aP);
    float4 ra1 = *(const float4*)(aP + rowStep);
    float4 rb0 = *(const float4*)(bP);
    float4 rb1 = *(const float4*)(bP + rowStep);

    const int nk = K >> 4;

    // stage tile 0 into buf 0
    {
        unsigned h, l;
        split2_bf16(ra0.x, ra0.y, h, l); sAh[0][w0  ][lrow] = h; sAl[0][w0  ][lrow] = l;
        split2_bf16(ra0.z, ra0.w, h, l); sAh[0][w0+1][lrow] = h; sAl[0][w0+1][lrow] = l;
        split2_bf16(ra1.x, ra1.y, h, l); sAh[0][w0  ][lrow+64] = h; sAl[0][w0  ][lrow+64] = l;
        split2_bf16(ra1.z, ra1.w, h, l); sAh[0][w0+1][lrow+64] = h; sAl[0][w0+1][lrow+64] = l;
        split2_bf16(rb0.x, rb0.y, h, l); sBh[0][w0  ][lrow] = h; sBl[0][w0  ][lrow] = l;
        split2_bf16(rb0.z, rb0.w, h, l); sBh[0][w0+1][lrow] = h; sBl[0][w0+1][lrow] = l;
        split2_bf16(rb1.x, rb1.y, h, l); sBh[0][w0  ][lrow+64] = h; sBl[0][w0  ][lrow+64] = l;
        split2_bf16(rb1.z, rb1.w, h, l); sBh[0][w0+1][lrow+64] = h; sBl[0][w0+1][lrow+64] = l;
    }
    __syncthreads();

    for (int kt = 0; kt < nk; kt++) {
        const int cur = kt & 1;
        const bool more = (kt + 1 < nk);
        if (more) {
            const float* aN = aP + (size_t)(kt + 1) * 16;
            const float* bN = bP + (size_t)(kt + 1) * 16;
            ra0 = *(const float4*)(aN);
            ra1 = *(const float4*)(aN + rowStep);
            rb0 = *(const float4*)(bN);
            rb1 = *(const float4*)(bN + rowStep);
        }

        // fragments for the full k-tile of 16
        unsigned ah[4][4], al[4][4], bh[4][2], bl[4][2];
        #pragma unroll
        for (int mt = 0; mt < 4; mt++) {
            int m = wm + (mt << 4) + gid;
            ah[mt][0] = sAh[cur][tig    ][m];
            ah[mt][1] = sAh[cur][tig    ][m + 8];
            ah[mt][2] = sAh[cur][tig + 4][m];
            ah[mt][3] = sAh[cur][tig + 4][m + 8];
            al[mt][0] = sAl[cur][tig    ][m];
            al[mt][1] = sAl[cur][tig    ][m + 8];
            al[mt][2] = sAl[cur][tig + 4][m];
            al[mt][3] = sAl[cur][tig + 4][m + 8];
        }
        #pragma unroll
        for (int nt = 0; nt < 4; nt++) {
            int n = wn + (nt << 3) + gid;
            bh[nt][0] = sBh[cur][tig    ][n];
            bh[nt][1] = sBh[cur][tig + 4][n];
            bl[nt][0] = sBl[cur][tig    ][n];
            bl[nt][1] = sBl[cur][tig + 4][n];
        }
        #pragma unroll
        for (int mt = 0; mt < 4; mt++)
            #pragma unroll
            for (int nt = 0; nt < 4; nt++) {
                MMA_BF16(acc[mt][nt], al[mt], bh[nt]);
                MMA_BF16(acc[mt][nt], ah[mt], bl[nt]);
                MMA_BF16(acc[mt][nt], ah[mt], bh[nt]);
            }

        if (more) {
            const int nxt = 1 - cur;
            unsigned h, l;
            split2_bf16(ra0.x, ra0.y, h, l); sAh[nxt][w0  ][lrow] = h; sAl[nxt][w0  ][lrow] = l;
            split2_bf16(ra0.z, ra0.w, h, l); sAh[nxt][w0+1][lrow] = h; sAl[nxt][w0+1][lrow] = l;
            split2_bf16(ra1.x, ra1.y, h, l); sAh[nxt][w0  ][lrow+64] = h; sAl[nxt][w0  ][lrow+64] = l;
            split2_bf16(ra1.z, ra1.w, h, l); sAh[nxt][w0+1][lrow+64] = h; sAl[nxt][w0+1][lrow+64] = l;
            split2_bf16(rb0.x, rb0.y, h, l); sBh[nxt][w0  ][lrow] = h; sBl[nxt][w0  ][lrow] = l;
            split2_bf16(rb0.z, rb0.w, h, l); sBh[nxt][w0+1][lrow] = h; sBl[nxt][w0+1][lrow] = l;
            split2_bf16(rb1.x, rb1.y, h, l); sBh[nxt][w0  ][lrow+64] = h; sBl[nxt][w0  ][lrow+64] = l;
            split2_bf16(rb1.z, rb1.w, h, l); sBh[nxt][w0+1][lrow+64] = h; sBl[nxt][w0+1][lrow+64] = l;
        }
        __syncthreads();
    }

    // epilogue
    const int rBase = (blockIdx.y << 7) + wm;
    const int cBase = (blockIdx.x << 7) + wn;
    #pragma unroll
    for (int mt = 0; mt < 4; mt++) {
        int r0 = rBase + (mt << 4) + gid;
        #pragma unroll
        for (int nt = 0; nt < 4; nt++) {
            int c = cBase + (nt << 3) + (tig << 1);
            size_t o0 = (size_t)r0 * N + c;
            size_t o1 = o0 + (size_t)8 * N;
            if (residual) {
                float2 q0 = *(const float2*)&residual[o0];
                float2 q1 = *(const float2*)&residual[o1];
                *(float2*)&C[o0] = make_float2(acc[mt][nt][0] + q0.x, acc[mt][nt][1] + q0.y);
                *(float2*)&C[o1] = make_float2(acc[mt][nt][2] + q1.x, acc[mt][nt][3] + q1.y);
            } else {
                *(float2*)&C[o0] = make_float2(acc[mt][nt][0], acc[mt][nt][1]);
                *(float2*)&C[o1] = make_float2(acc[mt][nt][2], acc[mt][nt][3]);
            }
        }
    }
}

// ---------------- RoPE in-place on q,k of qkv buffer ----------------
__global__ void rope_kernel(float* __restrict__ qkv) {
    int srow = blockIdx.x;
    float* row = qkv + (size_t)srow * H3;
    for (int it = threadIdx.x; it < 1024; it += 256) {
        int part = it >> 9;
        int rem  = it & 511;
        int h    = rem >> 5;
        int d    = rem & 31;
        float invf = powf(10000.f, -2.f * (float)d / 64.f);
        float ang  = (float)srow * invf;
        float sn, cs;
        sincosf(ang, &sn, &cs);
        float* p = row + part * H + h * 64;
        float x0 = p[d], x1 = p[d + 32];
        p[d]      = x0 * cs - x1 * sn;
        p[d + 32] = x1 * cs + x0 * sn;
    }
}

// ---------------- flash attention: 64-query x 64-key tiles, fp32 ----------------
__global__ void __launch_bounds__(256)
flash_attn_kernel(const float* __restrict__ qkv, float* __restrict__ out) {
    const int qt = blockIdx.x;
    const int h  = blockIdx.y;
    const int qbase = qt << 6;

    __shared__ float Qs [64][64];
    __shared__ float KVs[64][64];
    __shared__ float Ps [64][64];

    const int tid = threadIdx.x;
    const int ty = tid >> 4, tx = tid & 15;

    #pragma unroll
    for (int rep = 0; rep < 4; rep++) {
        int f = (rep << 8) + tid;
        int q = f >> 4;
        int d4 = (f & 15) << 2;
        float4 v = *(const float4*)&qkv[(size_t)(qbase + q) * H3 + h * 64 + d4];
        Qs[d4+0][q] = v.x * 0.125f;
        Qs[d4+1][q] = v.y * 0.125f;
        Qs[d4+2][q] = v.z * 0.125f;
        Qs[d4+3][q] = v.w * 0.125f;
    }

    float m_i[4], l_i[4], oacc[4][4];
    #pragma unroll
    for (int i = 0; i < 4; i++) {
        m_i[i] = -1e30f; l_i[i] = 0.f;
        #pragma unroll
        for (int j = 0; j < 4; j++) oacc[i][j] = 0.f;
    }

    for (int kt = 0; kt <= qt; kt++) {
        const int kbase = kt << 6;
        __syncthreads();
        #pragma unroll
        for (int rep = 0; rep < 4; rep++) {
            int f = (rep << 8) + tid;
            int k = f >> 4;
            int d4 = (f & 15) << 2;
            float4 v = *(const float4*)&qkv[(size_t)(kbase + k) * H3 + H + h * 64 + d4];
            KVs[d4+0][k] = v.x; KVs[d4+1][k] = v.y;
            KVs[d4+2][k] = v.z; KVs[d4+3][k] = v.w;
        }
        __syncthreads();

        float s[4][4];
        #pragma unroll
        for (int i = 0; i < 4; i++)
            #pragma unroll
            for (int j = 0; j < 4; j++) s[i][j] = 0.f;
        #pragma unroll 8
        for (int d = 0; d < 64; d++) {
            float4 a = *(const float4*)&Qs [d][ty << 2];
            float4 b = *(const float4*)&KVs[d][tx << 2];
            float av[4] = {a.x, a.y, a.z, a.w};
            float bv[4] = {b.x, b.y, b.z, b.w};
            #pragma unroll
            for (int i = 0; i < 4; i++)
                #pragma unroll
                for (int j = 0; j < 4; j++)
                    s[i][j] = fmaf(av[i], bv[j], s[i][j]);
        }
        if (kt == qt) {
            #pragma unroll
            for (int i = 0; i < 4; i++)
                #pragma unroll
                for (int j = 0; j < 4; j++)
                    if ((tx << 2) + j > (ty << 2) + i) s[i][j] = -1e30f;
        }

        #pragma unroll
        for (int i = 0; i < 4; i++) {
            float rmax = fmaxf(fmaxf(s[i][0], s[i][1]), fmaxf(s[i][2], s[i][3]));
            #pragma unroll
            for (int off = 8; off > 0; off >>= 1)
                rmax = fmaxf(rmax, __shfl_xor_sync(0xffffffffu, rmax, off));
            float mnew = fmaxf(m_i[i], rmax);
            float corr = __expf(m_i[i] - mnew);
            float rsum = 0.f;
            #pragma unroll
            for (int j = 0; j < 4; j++) {
                float p = __expf(s[i][j] - mnew);
                s[i][j] = p;
                rsum += p;
            }
            #pragma unroll
            for (int off = 8; off > 0; off >>= 1)
                rsum += __shfl_xor_sync(0xffffffffu, rsum, off);
            l_i[i] = l_i[i] * corr + rsum;
            m_i[i] = mnew;
            #pragma unroll
            for (int j = 0; j < 4; j++) oacc[i][j] *= corr;
        }
        __syncthreads();

        #pragma unroll
        for (int rep = 0; rep < 4; rep++) {
            int f = (rep << 8) + tid;
            int k = f >> 4;
            int d4 = (f & 15) << 2;
            float4 v = *(const float4*)&qkv[(size_t)(kbase + k) * H3 + 2 * H + h * 64 + d4];
            *(float4*)&KVs[k][d4] = v;
        }
        #pragma unroll
        for (int i = 0; i < 4; i++)
            #pragma unroll
            for (int j = 0; j < 4; j++)
                Ps[(tx << 2) + j][(ty << 2) + i] = s[i][j];
        __syncthreads();

        #pragma unroll 8
        for (int k = 0; k < 64; k++) {
            float4 a = *(const float4*)&Ps [k][ty << 2];
            float4 b = *(const float4*)&KVs[k][tx << 2];
            float av[4] = {a.x, a.y, a.z, a.w};
            float bv[4] = {b.x, b.y, b.z, b.w};
            #pragma unroll
            for (int i = 0; i < 4; i++)
                #pragma unroll
                for (int j = 0; j < 4; j++)
                    oacc[i][j] = fmaf(av[i], bv[j], oacc[i][j]);
        }
    }

    #pragma unroll
    for (int i = 0; i < 4; i++) {
        float inv = 1.f / l_i[i];
        int q = qbase + (ty << 2) + i;
        float4 v = make_float4(oacc[i][0] * inv, oacc[i][1] * inv,
                               oacc[i][2] * inv, oacc[i][3] * inv);
        *(float4*)&out[(size_t)q * H + h * 64 + (tx << 2)] = v;
    }
}

// ---------------- router ----------------
__global__ void router_kernel(const float* __restrict__ xn2, const float* __restrict__ rw) {
    int n = blockIdx.x;
    int tid = threadIdx.x;
    int e = tid >> 5, lane = tid & 31;
    const float* xr = xn2 + (size_t)n * H;
    const float* wr = rw + (size_t)e * H;
    float s = 0.f;
    for (int k = lane; k < H; k += 32) s += xr[k] * wr[k];
    #pragma unroll
    for (int off = 16; off > 0; off >>= 1) s += __shfl_down_sync(0xffffffff, s, off);
    __shared__ float logit[8];
    if (lane == 0) logit[e] = s;
    __syncthreads();
    if (tid == 0) {
        float mx = logit[0];
        for (int q = 1; q < 8; q++) mx = fmaxf(mx, logit[q]);
        float p[8]; float sum = 0.f;
        for (int q = 0; q < 8; q++) { p[q] = expf(logit[q] - mx); sum += p[q]; }
        for (int q = 0; q < 8; q++) p[q] /= sum;
        int b1 = 0;
        for (int q = 1; q < 8; q++) if (p[q] > p[b1]) b1 = q;
        int b2 = -1;
        for (int q = 0; q < 8; q++) {
            if (q == b1) continue;
            if (b2 < 0 || p[q] > p[b2]) b2 = q;
        }
        float ws = p[b1] + p[b2];
        g_e1[n] = b1; g_e2[n] = b2;
        g_w1[n] = p[b1] / ws; g_w2[n] = p[b2] / ws;
    }
}

// ---------------- slot assignment ----------------
__global__ void scan_kernel() {
    int w = threadIdx.x >> 5;
    int lane = threadIdx.x & 31;
    int base = 0;
    for (int c = 0; c < NTOK; c += 32) {
        int n = c + lane;
        int is1 = (g_e1[n] == w);
        int is2 = (g_e2[n] == w);
        int flag = is1 | is2;
        unsigned m = __ballot_sync(0xffffffff, flag);
        int pos = base + __popc(m & ((1u << lane) - 1u));
        if (flag) {
            int valid = pos < CAP;
            if (is1) { g_slot1[n] = pos; g_valid1[n] = valid; }
            else     { g_slot2[n] = pos; g_valid2[n] = valid; }
            if (valid) g_tok[w * CAP + pos] = n;
        }
        base += __popc(m);
    }
    if (lane == 0) {
        g_count[w] = base;
        g_count_used[w] = base < CAP ? base : CAP;
    }
}

// ---------------- gather ----------------
__global__ void gather_kernel() {
    int e = blockIdx.x >> 10;
    int slot = blockIdx.x & 1023;
    if (slot >= g_count_used[e]) return;
    int n = g_tok[e * CAP + slot];
    const float4* src = (const float4*)(g_xn2 + (size_t)n * H);
    float4* dst = (float4*)(g_Xg + ((size_t)e * CAP + slot) * H);
    dst[threadIdx.x] = src[threadIdx.x];
}

// ---------------- silu ----------------
__global__ void silu_kernel() {
    size_t idx = (size_t)blockIdx.x * 256 + threadIdx.x;
    int e   = (int)(idx / ((size_t)CAP * II));
    int row = (int)((idx / II) % CAP);
    if (row >= g_count_used[e]) return;
    float g = g_G[idx], u = g_U[idx];
    float sg = g / (1.f + __expf(-g));
    g_G[idx] = sg * u;
}

// ---------------- combine ----------------
__global__ void combine_kernel(float* __restrict__ out) {
    int n = blockIdx.x;
    int e1 = g_e1[n], e2 = g_e2[n];
    int s1 = g_slot1[n], s2 = g_slot2[n];
    int v1 = g_valid1[n], v2 = g_valid2[n];
    float w1 = g_w1[n], w2 = g_w2[n];
    const float* y1 = g_Y + ((size_t)e1 * CAP + (v1 ? s1 : 0)) * H;
    const float* y2 = g_Y + ((size_t)e2 * CAP + (v2 ? s2 : 0)) * H;
    for (int h = threadIdx.x; h < H; h += 256) {
        float acc = g_x1[(size_t)n * H + h];
        if (v1) acc += w1 * y1[h];
        if (v2) acc += w2 * y2[h];
        out[(size_t)n * H + h] = acc;
    }
}

// ---------------- aux loss ----------------
__global__ void aux_kernel(float* __restrict__ out, int out_size) {
    if (out_size <= S * H) return;
    float m[8], mu = 0.f;
    for (int e = 0; e < 8; e++) { m[e] = (float)g_count[e] / (float)NTOK; mu += m[e]; }
    mu *= 0.125f;
    float var = 0.f;
    for (int e = 0; e < 8; e++) { float d = m[e] - mu; var += d * d; }
    var /= 7.f;
    out[S * H] = var * 8.f;
}

// ---------------- launch ----------------
extern "C" void kernel_launch(void* const* d_in, const int* in_sizes, int n_in,
                              void* d_out, int out_size) {
    const float* x     = (const float*)d_in[0];
    const float* anw   = (const float*)d_in[1];
    const float* qkv_w = (const float*)d_in[2];
    const float* o_w   = (const float*)d_in[3];
    const float* fnw   = (const float*)d_in[4];
    const float* rw    = (const float*)d_in[5];
    const float* wg    = (const float*)d_in[6];
    const float* wu    = (const float*)d_in[7];
    const float* wd    = (const float*)d_in[8];
    float* out = (float*)d_out;

    float *p_xn, *p_qkv, *p_attn, *p_x1, *p_xn2, *p_Xg, *p_G, *p_U, *p_Y;
    int* p_cu;
    cudaGetSymbolAddress((void**)&p_xn,  g_xn);
    cudaGetSymbolAddress((void**)&p_qkv, g_qkv);
    cudaGetSymbolAddress((void**)&p_attn,g_attn);
    cudaGetSymbolAddress((void**)&p_x1,  g_x1);
    cudaGetSymbolAddress((void**)&p_xn2, g_xn2);
    cudaGetSymbolAddress((void**)&p_Xg,  g_Xg);
    cudaGetSymbolAddress((void**)&p_G,   g_G);
    cudaGetSymbolAddress((void**)&p_U,   g_U);
    cudaGetSymbolAddress((void**)&p_Y,   g_Y);
    cudaGetSymbolAddress((void**)&p_cu,  g_count_used);

    // attention path
    rmsnorm_kernel<<<S, 256>>>(x, anw, p_xn);
    bf16x3_gemm_kernel<<<dim3(H3 / 128, S / 128, 1), 256>>>(
        p_xn, qkv_w, p_qkv, nullptr, H3, H, 0, 0, 0, nullptr);
    rope_kernel<<<S, 256>>>(p_qkv);
    flash_attn_kernel<<<dim3(S / 64, NH), 256>>>(p_qkv, p_attn);
    bf16x3_gemm_kernel<<<dim3(H / 128, S / 128, 1), 256>>>(
        p_attn, o_w, p_x1, x, H, H, 0, 0, 0, nullptr);

    // MoE path
    rmsnorm_kernel<<<S, 256>>>(p_x1, fnw, p_xn2);
    router_kernel<<<S, 256>>>(p_xn2, rw);
    scan_kernel<<<1, 256>>>();
    gather_kernel<<<E * CAP, 256>>>();
    bf16x3_gemm_kernel<<<dim3(II / 128, CAP / 128, E), 256>>>(
        p_Xg, wg, p_G, nullptr, II, H,
        (size_t)CAP * H, (size_t)II * H, (size_t)CAP * II, p_cu);
    bf16x3_gemm_kernel<<<dim3(II / 128, CAP / 128, E), 256>>>(
        p_Xg, wu, p_U, nullptr, II, H,
        (size_t)CAP * H, (size_t)II * H, (size_t)CAP * II, p_cu);
    silu_kernel<<<(E * CAP * (II / 256)), 256>>>();
    bf16x3_gemm_kernel<<<dim3(H / 128, CAP / 128, E), 256>>>(
        p_G, wd, p_Y, nullptr, H, II,
        (size_t)CAP * II, (size_t)H * II, (size_t)CAP * H, p_cu);
    combine_kernel<<<S, 256>>>(out);
    aux_kernel<<<1, 1>>>(out, out_size);
}

// round 5
// speedup vs baseline: 3.5788x; 1.1100x over previous
#include <cuda_runtime.h>
#include <cuda_bf16.h>
#include <math.h>

#define S    2048
#define H    1024
#define NH   16
#define HD   64
#define H3   3072
#define E    8
#define II   4096
#define CAP  1024
#define NTOK S

// ---------------- scratch (device globals; no allocation allowed) ----------------
__device__ float g_xn  [S*H];
__device__ float g_qkv [S*H3];
__device__ float g_attn[S*H];
__device__ float g_x1  [S*H];
__device__ float g_xn2 [S*H];
__device__ float g_Xg  [E*CAP*H];
__device__ float g_G   [(size_t)E*CAP*II];
__device__ float g_U   [(size_t)E*CAP*II];
__device__ float g_Y   [E*CAP*H];

// bf16 hi/lo split buffers for attention (mma-ready layouts)
__device__ unsigned short g_Qh[NH*S*64], g_Ql[NH*S*64];
__device__ unsigned short g_Kh[NH*S*64], g_Kl[NH*S*64];
__device__ unsigned g_Vh[NH*(S/2)*64], g_Vl[NH*(S/2)*64];

__device__ int   g_e1[NTOK], g_e2[NTOK];
__device__ float g_w1[NTOK], g_w2[NTOK];
__device__ int   g_slot1[NTOK], g_slot2[NTOK];
__device__ int   g_valid1[NTOK], g_valid2[NTOK];
__device__ int   g_tok[E*CAP];
__device__ int   g_count[E];
__device__ int   g_count_used[E];

// ---------------- RMSNorm ----------------
__global__ void rmsnorm_kernel(const float* __restrict__ x,
                               const float* __restrict__ w,
                               float* __restrict__ out) {
    int row = blockIdx.x;
    const float* xr = x + (size_t)row * H;
    float s = 0.f;
    for (int i = threadIdx.x; i < H; i += 256) { float v = xr[i]; s += v * v; }
    __shared__ float red[256];
    red[threadIdx.x] = s; __syncthreads();
    for (int off = 128; off > 0; off >>= 1) {
        if (threadIdx.x < off) red[threadIdx.x] += red[threadIdx.x + off];
        __syncthreads();
    }
    float inv = rsqrtf(red[0] / (float)H + 1e-6f);
    for (int i = threadIdx.x; i < H; i += 256)
        out[(size_t)row * H + i] = xr[i] * inv * w[i];
}

// ------- 3xBF16 tensor-core GEMM: C[M,N] = A[M,K]*B[N,K]^T (+residual) -----------
__device__ __forceinline__ void split2_bf16(float f0, float f1,
                                            unsigned& hi, unsigned& lo) {
    __nv_bfloat16 h0 = __float2bfloat16_rn(f0);
    __nv_bfloat16 h1 = __float2bfloat16_rn(f1);
    float r0 = f0 - __bfloat162float(h0);
    float r1 = f1 - __bfloat162float(h1);
    __nv_bfloat16 l0 = __float2bfloat16_rn(r0);
    __nv_bfloat16 l1 = __float2bfloat16_rn(r1);
    hi = ((unsigned)__bfloat16_as_ushort(h1) << 16) | __bfloat16_as_ushort(h0);
    lo = ((unsigned)__bfloat16_as_ushort(l1) << 16) | __bfloat16_as_ushort(l0);
}

#define MMA_BF16(acc, a, b)                                               \
    asm volatile(                                                         \
        "mma.sync.aligned.m16n8k16.row.col.f32.bf16.bf16.f32 "            \
        "{%0,%1,%2,%3}, {%4,%5,%6,%7}, {%8,%9}, {%0,%1,%2,%3};"           \
        : "+f"(acc[0]), "+f"(acc[1]), "+f"(acc[2]), "+f"(acc[3])          \
        : "r"(a[0]), "r"(a[1]), "r"(a[2]), "r"(a[3]), "r"(b[0]), "r"(b[1]))

__global__ void __launch_bounds__(256)
bf16x3_gemm_kernel(const float* __restrict__ A, const float* __restrict__ B,
                   float* __restrict__ C, const float* __restrict__ residual,
                   int N, int K,
                   size_t aStride, size_t bStride, size_t cStride,
                   const int* __restrict__ counts) {
    int z = blockIdx.z;
    if (counts && (int)(blockIdx.y << 7) >= counts[z]) return;
    A += (size_t)z * aStride + ((size_t)blockIdx.y << 7) * K;
    B += (size_t)z * bStride + ((size_t)blockIdx.x << 7) * K;
    C += (size_t)z * cStride;

    __shared__ unsigned sAh[2][8][136], sAl[2][8][136];
    __shared__ unsigned sBh[2][8][136], sBl[2][8][136];

    const int tid  = threadIdx.x;
    const int lrow = tid >> 2;
    const int lcol = (tid & 3) << 2;
    const int w0   = (tid & 3) << 1;

    const float* aP = A + (size_t)lrow * K + lcol;
    const float* bP = B + (size_t)lrow * K + lcol;
    const size_t rowStep = (size_t)64 * K;

    const int lane = tid & 31;
    const int wid  = tid >> 5;
    const int gid  = lane >> 2, tig = lane & 3;
    const int wm   = (wid >> 2) * 64;
    const int wn   = (wid & 3) * 32;

    float acc[4][4][4];
    #pragma unroll
    for (int i = 0; i < 4; i++)
        #pragma unroll
        for (int j = 0; j < 4; j++)
            #pragma unroll
            for (int r = 0; r < 4; r++) acc[i][j][r] = 0.f;

    float4 ra0 = *(const float4*)(aP);
    float4 ra1 = *(const float4*)(aP + rowStep);
    float4 rb0 = *(const float4*)(bP);
    float4 rb1 = *(const float4*)(bP + rowStep);

    const int nk = K >> 4;

    {
        unsigned h, l;
        split2_bf16(ra0.x, ra0.y, h, l); sAh[0][w0  ][lrow] = h; sAl[0][w0  ][lrow] = l;
        split2_bf16(ra0.z, ra0.w, h, l); sAh[0][w0+1][lrow] = h; sAl[0][w0+1][lrow] = l;
        split2_bf16(ra1.x, ra1.y, h, l); sAh[0][w0  ][lrow+64] = h; sAl[0][w0  ][lrow+64] = l;
        split2_bf16(ra1.z, ra1.w, h, l); sAh[0][w0+1][lrow+64] = h; sAl[0][w0+1][lrow+64] = l;
        split2_bf16(rb0.x, rb0.y, h, l); sBh[0][w0  ][lrow] = h; sBl[0][w0  ][lrow] = l;
        split2_bf16(rb0.z, rb0.w, h, l); sBh[0][w0+1][lrow] = h; sBl[0][w0+1][lrow] = l;
        split2_bf16(rb1.x, rb1.y, h, l); sBh[0][w0  ][lrow+64] = h; sBl[0][w0  ][lrow+64] = l;
        split2_bf16(rb1.z, rb1.w, h, l); sBh[0][w0+1][lrow+64] = h; sBl[0][w0+1][lrow+64] = l;
    }
    __syncthreads();

    for (int kt = 0; kt < nk; kt++) {
        const int cur = kt & 1;
        const bool more = (kt + 1 < nk);
        if (more) {
            const float* aN = aP + (size_t)(kt + 1) * 16;
            const float* bN = bP + (size_t)(kt + 1) * 16;
            ra0 = *(const float4*)(aN);
            ra1 = *(const float4*)(aN + rowStep);
            rb0 = *(const float4*)(bN);
            rb1 = *(const float4*)(bN + rowStep);
        }

        unsigned ah[4][4], al[4][4], bh[4][2], bl[4][2];
        #pragma unroll
        for (int mt = 0; mt < 4; mt++) {
            int m = wm + (mt << 4) + gid;
            ah[mt][0] = sAh[cur][tig    ][m];
            ah[mt][1] = sAh[cur][tig    ][m + 8];
            ah[mt][2] = sAh[cur][tig + 4][m];
            ah[mt][3] = sAh[cur][tig + 4][m + 8];
            al[mt][0] = sAl[cur][tig    ][m];
            al[mt][1] = sAl[cur][tig    ][m + 8];
            al[mt][2] = sAl[cur][tig + 4][m];
            al[mt][3] = sAl[cur][tig + 4][m + 8];
        }
        #pragma unroll
        for (int nt = 0; nt < 4; nt++) {
            int n = wn + (nt << 3) + gid;
            bh[nt][0] = sBh[cur][tig    ][n];
            bh[nt][1] = sBh[cur][tig + 4][n];
            bl[nt][0] = sBl[cur][tig    ][n];
            bl[nt][1] = sBl[cur][tig + 4][n];
        }
        #pragma unroll
        for (int mt = 0; mt < 4; mt++)
            #pragma unroll
            for (int nt = 0; nt < 4; nt++) {
                MMA_BF16(acc[mt][nt], al[mt], bh[nt]);
                MMA_BF16(acc[mt][nt], ah[mt], bl[nt]);
                MMA_BF16(acc[mt][nt], ah[mt], bh[nt]);
            }

        if (more) {
            const int nxt = 1 - cur;
            unsigned h, l;
            split2_bf16(ra0.x, ra0.y, h, l); sAh[nxt][w0  ][lrow] = h; sAl[nxt][w0  ][lrow] = l;
            split2_bf16(ra0.z, ra0.w, h, l); sAh[nxt][w0+1][lrow] = h; sAl[nxt][w0+1][lrow] = l;
            split2_bf16(ra1.x, ra1.y, h, l); sAh[nxt][w0  ][lrow+64] = h; sAl[nxt][w0  ][lrow+64] = l;
            split2_bf16(ra1.z, ra1.w, h, l); sAh[nxt][w0+1][lrow+64] = h; sAl[nxt][w0+1][lrow+64] = l;
            split2_bf16(rb0.x, rb0.y, h, l); sBh[nxt][w0  ][lrow] = h; sBl[nxt][w0  ][lrow] = l;
            split2_bf16(rb0.z, rb0.w, h, l); sBh[nxt][w0+1][lrow] = h; sBl[nxt][w0+1][lrow] = l;
            split2_bf16(rb1.x, rb1.y, h, l); sBh[nxt][w0  ][lrow+64] = h; sBl[nxt][w0  ][lrow+64] = l;
            split2_bf16(rb1.z, rb1.w, h, l); sBh[nxt][w0+1][lrow+64] = h; sBl[nxt][w0+1][lrow+64] = l;
        }
        __syncthreads();
    }

    const int rBase = (blockIdx.y << 7) + wm;
    const int cBase = (blockIdx.x << 7) + wn;
    #pragma unroll
    for (int mt = 0; mt < 4; mt++) {
        int r0 = rBase + (mt << 4) + gid;
        #pragma unroll
        for (int nt = 0; nt < 4; nt++) {
            int c = cBase + (nt << 3) + (tig << 1);
            size_t o0 = (size_t)r0 * N + c;
            size_t o1 = o0 + (size_t)8 * N;
            if (residual) {
                float2 q0 = *(const float2*)&residual[o0];
                float2 q1 = *(const float2*)&residual[o1];
                *(float2*)&C[o0] = make_float2(acc[mt][nt][0] + q0.x, acc[mt][nt][1] + q0.y);
                *(float2*)&C[o1] = make_float2(acc[mt][nt][2] + q1.x, acc[mt][nt][3] + q1.y);
            } else {
                *(float2*)&C[o0] = make_float2(acc[mt][nt][0], acc[mt][nt][1]);
                *(float2*)&C[o1] = make_float2(acc[mt][nt][2], acc[mt][nt][3]);
            }
        }
    }
}

// -------- prep: RoPE on q,k + bf16 hi/lo split into mma-ready buffers ------------
__global__ void prep_qk_kernel(const float* __restrict__ qkv) {
    int s = blockIdx.x;
    const float* row = qkv + (size_t)s * H3;
    for (int rep = 0; rep < 4; rep++) {
        int it = threadIdx.x + (rep << 8);
        int part = it >> 9;          // 0=q, 1=k
        int rem  = it & 511;
        int h    = rem >> 5;
        int d    = rem & 31;         // pair index
        float invf = powf(10000.f, -2.f * (float)d / 64.f);
        float ang  = (float)s * invf;
        float sn, cs;
        sincosf(ang, &sn, &cs);
        const float* p = row + part * H + h * 64;
        float x0 = p[d], x1 = p[d + 32];
        float y0 = x0 * cs - x1 * sn;
        float y1 = x1 * cs + x0 * sn;
        if (part == 0) { y0 *= 0.125f; y1 *= 0.125f; }
        unsigned short* Hb = part ? g_Kh : g_Qh;
        unsigned short* Lb = part ? g_Kl : g_Ql;
        size_t base = ((size_t)h * S + s) * 64;
        __nv_bfloat16 h0 = __float2bfloat16_rn(y0);
        __nv_bfloat16 l0 = __float2bfloat16_rn(y0 - __bfloat162float(h0));
        Hb[base + d] = __bfloat16_as_ushort(h0);
        Lb[base + d] = __bfloat16_as_ushort(l0);
        __nv_bfloat16 h1 = __float2bfloat16_rn(y1);
        __nv_bfloat16 l1 = __float2bfloat16_rn(y1 - __bfloat162float(h1));
        Hb[base + d + 32] = __bfloat16_as_ushort(h1);
        Lb[base + d + 32] = __bfloat16_as_ushort(l1);
    }
}

// -------- prep: V split + key-pair transpose (B-fragment-ready) ------------------
__global__ void vtrans_kernel(const float* __restrict__ qkv) {
    int w = blockIdx.x;   // key pair index (0..S/2-1)
    int h = blockIdx.y;
    int d = threadIdx.x;  // 0..63
    float v0 = qkv[(size_t)(2 * w)     * H3 + 2 * H + h * 64 + d];
    float v1 = qkv[(size_t)(2 * w + 1) * H3 + 2 * H + h * 64 + d];
    unsigned hi, lo;
    split2_bf16(v0, v1, hi, lo);
    size_t idx = ((size_t)h * (S / 2) + w) * 64 + d;
    g_Vh[idx] = hi;
    g_Vl[idx] = lo;
}

// -------- flash attention, tensor cores: 128q x 64k tiles, bf16x3 ----------------
__global__ void __launch_bounds__(256)
flash2_kernel(float* __restrict__ out) {
    const int qt = gridDim.x - 1 - blockIdx.x;   // large-qt blocks first
    const int h  = blockIdx.y;
    const int qbase = qt << 7;

    __shared__ unsigned sKh[32][65], sKl[32][65];
    __shared__ unsigned sVh[32][65], sVl[32][65];

    const int tid  = threadIdx.x;
    const int wid  = tid >> 5;
    const int lane = tid & 31;
    const int gid  = lane >> 2, tig = lane & 3;
    const int m0   = wid << 4;

    const unsigned* Qh32 = (const unsigned*)g_Qh;
    const unsigned* Ql32 = (const unsigned*)g_Ql;
    const unsigned* Kh32 = (const unsigned*)g_Kh;
    const unsigned* Kl32 = (const unsigned*)g_Kl;

    // persistent Q fragments (rows m0+gid, m0+gid+8)
    unsigned qh_f[4][4], ql_f[4][4];
    {
        size_t r0 = ((size_t)h * S + qbase + m0 + gid) * 32;
        size_t r1 = r0 + 8 * 32;
        #pragma unroll
        for (int kk = 0; kk < 4; kk++) {
            int w = (kk << 3) + tig;
            qh_f[kk][0] = Qh32[r0 + w];     qh_f[kk][1] = Qh32[r1 + w];
            qh_f[kk][2] = Qh32[r0 + w + 4]; qh_f[kk][3] = Qh32[r1 + w + 4];
            ql_f[kk][0] = Ql32[r0 + w];     ql_f[kk][1] = Ql32[r1 + w];
            ql_f[kk][2] = Ql32[r0 + w + 4]; ql_f[kk][3] = Ql32[r1 + w + 4];
        }
    }

    float m_i[2] = {-1e30f, -1e30f};
    float l_i[2] = {0.f, 0.f};
    float oacc[8][4];
    #pragma unroll
    for (int i = 0; i < 8; i++)
        #pragma unroll
        for (int j = 0; j < 4; j++) oacc[i][j] = 0.f;

    const int nkt = 2 * qt + 2;
    for (int kt = 0; kt < nkt; kt++) {
        const int kbase = kt << 6;
        __syncthreads();
        #pragma unroll
        for (int i = 0; i < 8; i++) {
            int idx = tid + (i << 8);          // 0..2047
            int r = idx >> 5, w = idx & 31;
            size_t gk = ((size_t)h * S + kbase + r) * 32 + w;
            sKh[w][r] = Kh32[gk];
            sKl[w][r] = Kl32[gk];
            int wv = idx >> 6, dv = idx & 63;
            size_t gv = ((size_t)h * (S / 2) + (kbase >> 1) + wv) * 64 + dv;
            sVh[wv][dv] = g_Vh[gv];
            sVl[wv][dv] = g_Vl[gv];
        }
        __syncthreads();

        // scores
        float s[8][4];
        #pragma unroll
        for (int nt = 0; nt < 8; nt++)
            #pragma unroll
            for (int j = 0; j < 4; j++) s[nt][j] = 0.f;
        #pragma unroll
        for (int nt = 0; nt < 8; nt++) {
            int n = (nt << 3) + gid;
            #pragma unroll
            for (int kk = 0; kk < 4; kk++) {
                unsigned bh[2] = {sKh[(kk << 3) + tig][n], sKh[(kk << 3) + tig + 4][n]};
                unsigned bl[2] = {sKl[(kk << 3) + tig][n], sKl[(kk << 3) + tig + 4][n]};
                MMA_BF16(s[nt], ql_f[kk], bh);
                MMA_BF16(s[nt], qh_f[kk], bl);
                MMA_BF16(s[nt], qh_f[kk], bh);
            }
        }

        // causal mask
        if (kbase + 63 > qbase + m0) {
            int r0 = qbase + m0 + gid, r1 = r0 + 8;
            #pragma unroll
            for (int nt = 0; nt < 8; nt++) {
                int c0 = kbase + (nt << 3) + (tig << 1);
                int c1 = c0 + 1;
                if (c0 > r0) s[nt][0] = -1e30f;
                if (c1 > r0) s[nt][1] = -1e30f;
                if (c0 > r1) s[nt][2] = -1e30f;
                if (c1 > r1) s[nt][3] = -1e30f;
            }
        }

        // online softmax: row0 = gid row (regs 0,1), row1 = gid+8 (regs 2,3)
        float rmax0 = -1e30f, rmax1 = -1e30f;
        #pragma unroll
        for (int nt = 0; nt < 8; nt++) {
            rmax0 = fmaxf(rmax0, fmaxf(s[nt][0], s[nt][1]));
            rmax1 = fmaxf(rmax1, fmaxf(s[nt][2], s[nt][3]));
        }
        #pragma unroll
        for (int off = 1; off <= 2; off <<= 1) {
            rmax0 = fmaxf(rmax0, __shfl_xor_sync(0xffffffffu, rmax0, off));
            rmax1 = fmaxf(rmax1, __shfl_xor_sync(0xffffffffu, rmax1, off));
        }
        float mnew0 = fmaxf(m_i[0], rmax0);
        float mnew1 = fmaxf(m_i[1], rmax1);
        float corr0 = __expf(m_i[0] - mnew0);
        float corr1 = __expf(m_i[1] - mnew1);
        float sum0 = 0.f, sum1 = 0.f;
        #pragma unroll
        for (int nt = 0; nt < 8; nt++) {
            s[nt][0] = __expf(s[nt][0] - mnew0); sum0 += s[nt][0];
            s[nt][1] = __expf(s[nt][1] - mnew0); sum0 += s[nt][1];
            s[nt][2] = __expf(s[nt][2] - mnew1); sum1 += s[nt][2];
            s[nt][3] = __expf(s[nt][3] - mnew1); sum1 += s[nt][3];
        }
        #pragma unroll
        for (int off = 1; off <= 2; off <<= 1) {
            sum0 += __shfl_xor_sync(0xffffffffu, sum0, off);
            sum1 += __shfl_xor_sync(0xffffffffu, sum1, off);
        }
        l_i[0] = l_i[0] * corr0 + sum0;
        l_i[1] = l_i[1] * corr1 + sum1;
        m_i[0] = mnew0;
        m_i[1] = mnew1;
        #pragma unroll
        for (int nt = 0; nt < 8; nt++) {
            oacc[nt][0] *= corr0; oacc[nt][1] *= corr0;
            oacc[nt][2] *= corr1; oacc[nt][3] *= corr1;
        }

        // P*V: P fragments built in registers from score accumulators
        #pragma unroll
        for (int kk = 0; kk < 4; kk++) {
            unsigned ph[4], pl[4];
            split2_bf16(s[2*kk  ][0], s[2*kk  ][1], ph[0], pl[0]);
            split2_bf16(s[2*kk  ][2], s[2*kk  ][3], ph[1], pl[1]);
            split2_bf16(s[2*kk+1][0], s[2*kk+1][1], ph[2], pl[2]);
            split2_bf16(s[2*kk+1][2], s[2*kk+1][3], ph[3], pl[3]);
            #pragma unroll
            for (int ntd = 0; ntd < 8; ntd++) {
                int dcol = (ntd << 3) + gid;
                unsigned vh[2] = {sVh[(kk << 3) + tig][dcol], sVh[(kk << 3) + tig + 4][dcol]};
                unsigned vl[2] = {sVl[(kk << 3) + tig][dcol], sVl[(kk << 3) + tig + 4][dcol]};
                MMA_BF16(oacc[ntd], pl, vh);
                MMA_BF16(oacc[ntd], ph, vl);
                MMA_BF16(oacc[ntd], ph, vh);
            }
        }
    }

    // epilogue
    float inv0 = 1.f / l_i[0];
    float inv1 = 1.f / l_i[1];
    int r0 = qbase + m0 + gid;
    #pragma unroll
    for (int ntd = 0; ntd < 8; ntd++) {
        int d = (ntd << 3) + (tig << 1);
        *(float2*)&out[(size_t)r0 * H + h * 64 + d] =
            make_float2(oacc[ntd][0] * inv0, oacc[ntd][1] * inv0);
        *(float2*)&out[(size_t)(r0 + 8) * H + h * 64 + d] =
            make_float2(oacc[ntd][2] * inv1, oacc[ntd][3] * inv1);
    }
}

// ---------------- router ----------------
__global__ void router_kernel(const float* __restrict__ xn2, const float* __restrict__ rw) {
    int n = blockIdx.x;
    int tid = threadIdx.x;
    int e = tid >> 5, lane = tid & 31;
    const float* xr = xn2 + (size_t)n * H;
    const float* wr = rw + (size_t)e * H;
    float s = 0.f;
    for (int k = lane; k < H; k += 32) s += xr[k] * wr[k];
    #pragma unroll
    for (int off = 16; off > 0; off >>= 1) s += __shfl_down_sync(0xffffffff, s, off);
    __shared__ float logit[8];
    if (lane == 0) logit[e] = s;
    __syncthreads();
    if (tid == 0) {
        float mx = logit[0];
        for (int q = 1; q < 8; q++) mx = fmaxf(mx, logit[q]);
        float p[8]; float sum = 0.f;
        for (int q = 0; q < 8; q++) { p[q] = expf(logit[q] - mx); sum += p[q]; }
        for (int q = 0; q < 8; q++) p[q] /= sum;
        int b1 = 0;
        for (int q = 1; q < 8; q++) if (p[q] > p[b1]) b1 = q;
        int b2 = -1;
        for (int q = 0; q < 8; q++) {
            if (q == b1) continue;
            if (b2 < 0 || p[q] > p[b2]) b2 = q;
        }
        float ws = p[b1] + p[b2];
        g_e1[n] = b1; g_e2[n] = b2;
        g_w1[n] = p[b1] / ws; g_w2[n] = p[b2] / ws;
    }
}

// ---------------- slot assignment ----------------
__global__ void scan_kernel() {
    int w = threadIdx.x >> 5;
    int lane = threadIdx.x & 31;
    int base = 0;
    for (int c = 0; c < NTOK; c += 32) {
        int n = c + lane;
        int is1 = (g_e1[n] == w);
        int is2 = (g_e2[n] == w);
        int flag = is1 | is2;
        unsigned m = __ballot_sync(0xffffffff, flag);
        int pos = base + __popc(m & ((1u << lane) - 1u));
        if (flag) {
            int valid = pos < CAP;
            if (is1) { g_slot1[n] = pos; g_valid1[n] = valid; }
            else     { g_slot2[n] = pos; g_valid2[n] = valid; }
            if (valid) g_tok[w * CAP + pos] = n;
        }
        base += __popc(m);
    }
    if (lane == 0) {
        g_count[w] = base;
        g_count_used[w] = base < CAP ? base : CAP;
    }
}

// ---------------- gather ----------------
__global__ void gather_kernel() {
    int e = blockIdx.x >> 10;
    int slot = blockIdx.x & 1023;
    if (slot >= g_count_used[e]) return;
    int n = g_tok[e * CAP + slot];
    const float4* src = (const float4*)(g_xn2 + (size_t)n * H);
    float4* dst = (float4*)(g_Xg + ((size_t)e * CAP + slot) * H);
    dst[threadIdx.x] = src[threadIdx.x];
}

// ---------------- silu ----------------
__global__ void silu_kernel() {
    size_t idx = (size_t)blockIdx.x * 256 + threadIdx.x;
    int e   = (int)(idx / ((size_t)CAP * II));
    int row = (int)((idx / II) % CAP);
    if (row >= g_count_used[e]) return;
    float g = g_G[idx], u = g_U[idx];
    float sg = g / (1.f + __expf(-g));
    g_G[idx] = sg * u;
}

// ---------------- combine ----------------
__global__ void combine_kernel(float* __restrict__ out) {
    int n = blockIdx.x;
    int e1 = g_e1[n], e2 = g_e2[n];
    int s1 = g_slot1[n], s2 = g_slot2[n];
    int v1 = g_valid1[n], v2 = g_valid2[n];
    float w1 = g_w1[n], w2 = g_w2[n];
    const float* y1 = g_Y + ((size_t)e1 * CAP + (v1 ? s1 : 0)) * H;
    const float* y2 = g_Y + ((size_t)e2 * CAP + (v2 ? s2 : 0)) * H;
    for (int h = threadIdx.x; h < H; h += 256) {
        float acc = g_x1[(size_t)n * H + h];
        if (v1) acc += w1 * y1[h];
        if (v2) acc += w2 * y2[h];
        out[(size_t)n * H + h] = acc;
    }
}

// ---------------- aux loss ----------------
__global__ void aux_kernel(float* __restrict__ out, int out_size) {
    if (out_size <= S * H) return;
    float m[8], mu = 0.f;
    for (int e = 0; e < 8; e++) { m[e] = (float)g_count[e] / (float)NTOK; mu += m[e]; }
    mu *= 0.125f;
    float var = 0.f;
    for (int e = 0; e < 8; e++) { float d = m[e] - mu; var += d * d; }
    var /= 7.f;
    out[S * H] = var * 8.f;
}

// ---------------- launch ----------------
extern "C" void kernel_launch(void* const* d_in, const int* in_sizes, int n_in,
                              void* d_out, int out_size) {
    const float* x     = (const float*)d_in[0];
    const float* anw   = (const float*)d_in[1];
    const float* qkv_w = (const float*)d_in[2];
    const float* o_w   = (const float*)d_in[3];
    const float* fnw   = (const float*)d_in[4];
    const float* rw    = (const float*)d_in[5];
    const float* wg    = (const float*)d_in[6];
    const float* wu    = (const float*)d_in[7];
    const float* wd    = (const float*)d_in[8];
    float* out = (float*)d_out;

    float *p_xn, *p_qkv, *p_attn, *p_x1, *p_xn2, *p_Xg, *p_G, *p_U, *p_Y;
    int* p_cu;
    cudaGetSymbolAddress((void**)&p_xn,  g_xn);
    cudaGetSymbolAddress((void**)&p_qkv, g_qkv);
    cudaGetSymbolAddress((void**)&p_attn,g_attn);
    cudaGetSymbolAddress((void**)&p_x1,  g_x1);
    cudaGetSymbolAddress((void**)&p_xn2, g_xn2);
    cudaGetSymbolAddress((void**)&p_Xg,  g_Xg);
    cudaGetSymbolAddress((void**)&p_G,   g_G);
    cudaGetSymbolAddress((void**)&p_U,   g_U);
    cudaGetSymbolAddress((void**)&p_Y,   g_Y);
    cudaGetSymbolAddress((void**)&p_cu,  g_count_used);

    // attention path
    rmsnorm_kernel<<<S, 256>>>(x, anw, p_xn);
    bf16x3_gemm_kernel<<<dim3(H3 / 128, S / 128, 1), 256>>>(
        p_xn, qkv_w, p_qkv, nullptr, H3, H, 0, 0, 0, nullptr);
    prep_qk_kernel<<<S, 256>>>(p_qkv);
    vtrans_kernel<<<dim3(S / 2, NH), 64>>>(p_qkv);
    flash2_kernel<<<dim3(S / 128, NH), 256>>>(p_attn);
    bf16x3_gemm_kernel<<<dim3(H / 128, S / 128, 1), 256>>>(
        p_attn, o_w, p_x1, x, H, H, 0, 0, 0, nullptr);

    // MoE path
    rmsnorm_kernel<<<S, 256>>>(p_x1, fnw, p_xn2);
    router_kernel<<<S, 256>>>(p_xn2, rw);
    scan_kernel<<<1, 256>>>();
    gather_kernel<<<E * CAP, 256>>>();
    bf16x3_gemm_kernel<<<dim3(II / 128, CAP / 128, E), 256>>>(
        p_Xg, wg, p_G, nullptr, II, H,
        (size_t)CAP * H, (size_t)II * H, (size_t)CAP * II, p_cu);
    bf16x3_gemm_kernel<<<dim3(II / 128, CAP / 128, E), 256>>>(
        p_Xg, wu, p_U, nullptr, II, H,
        (size_t)CAP * H, (size_t)II * H, (size_t)CAP * II, p_cu);
    silu_kernel<<<(E * CAP * (II / 256)), 256>>>();
    bf16x3_gemm_kernel<<<dim3(H / 128, CAP / 128, E), 256>>>(
        p_G, wd, p_Y, nullptr, H, II,
        (size_t)CAP * II, (size_t)H * II, (size_t)CAP * H, p_cu);
    combine_kernel<<<S, 256>>>(out);
    aux_kernel<<<1, 1>>>(out, out_size);
}